// round 7
// baseline (speedup 1.0000x reference)
#include <cuda_runtime.h>

// INRF: out[b,i,j,c] = sum_yx M[ij,yx]*in[b,yx,c]
//                    - L * sum_yx W[ij,yx]*relu(in[b,yx,c] - shifted[b,ij,yx,c])
// shifted[b,ij,y,x,f] = sum_{kh,kw,c} in[b,y+kh-1,x+kw-1,c] * G[ij,kh,kw,c,f]
// B=4, H=W=32, C=F=16, KH=KW=3, L=1, SAME padding.
//
// One CTA per (i,j), 512 threads, 2 spatial positions per thread.
// SMEM: G[ij] (2304f), M/W rows, channel-major zero-padded input [16][34][34].
// Inner loop: packed fma.rn.f32x2 over the 16 filters (8 lane-pairs).
// All pack/unpack is plain C bit arithmetic; the ONLY inline asm is the
// fma.rn.f32x2 itself (same form as production ptx_helpers macros).
// (Resubmission of R5 kernel - previous round hit a container infra failure.)

typedef unsigned long long u64;
#define FULLMASK 0xFFFFFFFFu

#define FMA2(d, a, b, c) \
    asm("fma.rn.f32x2 %0, %1, %2, %3;" : "=l"(d) : "l"(a), "l"(b), "l"(c))

__device__ __forceinline__ u64 pk(float x) {
    u64 v = (u64)__float_as_uint(x);
    return v | (v << 32);
}
__device__ __forceinline__ float lo32(u64 v) {
    return __uint_as_float((unsigned)v);
}
__device__ __forceinline__ float hi32(u64 v) {
    return __uint_as_float((unsigned)(v >> 32));
}

// SMEM layout (floats):
//  [0,2304)        G[ij]  : [kh][kw][c][f]   (f contiguous, 8 u64 pairs)
//  [2304,3328)     M row  : 1024
//  [3328,4352)     W row  : 1024
//  [4352,22848)    input tile, channel-major padded: [16][34][34]
//  [22848,23360)   reduction buffer (16 warps x 16 + pad)
#define OFF_M   2304
#define OFF_W   3328
#define OFF_IN  4352
#define OFF_RED 22848
#define SMEM_FLOATS 23360
#define SMEM_BYTES  (SMEM_FLOATS * 4)
#define IN_T (16 * 34 * 34)   // 18496

__global__ __launch_bounds__(512)
void inrf_kernel(const float* __restrict__ in,   // [4][32][32][16]
                 const float* __restrict__ Mm,   // [1024][1024]
                 const float* __restrict__ Ww,   // [1024][1024]
                 const float* __restrict__ Gg,   // [1024][3][3][16][16]
                 float* __restrict__ out)        // [4][32][32][16]
{
    extern __shared__ float sm[];
    float* sG   = sm;
    float* sM   = sm + OFF_M;
    float* sW   = sm + OFF_W;
    float* sIn  = sm + OFF_IN;
    float* sRed = sm + OFF_RED;

    const int ij = blockIdx.x;       // 0..1023
    const int t  = threadIdx.x;      // 0..511
    const int warp = t >> 5, lane = t & 31;

    // Load per-(i,j) weights
    for (int i = t; i < 2304; i += 512) sG[i] = Gg[ij * 2304 + i];
    for (int i = t; i < 1024; i += 512) {
        sM[i] = Mm[ij * 1024 + i];
        sW[i] = Ww[ij * 1024 + i];
    }

    // This thread's 2 positions: yx0 = t (y0 = t>>5), yx1 = t+512 (y0+16)
    const int y0 = t >> 5;
    const int x0 = t & 31;

    for (int b = 0; b < 4; b++) {
        __syncthreads();  // protect sIn (and sRed/sG on first iter)
        // Load image b, channel-major, zero-padded: sIn[c*1156 + (y+1)*34 + (x+1)]
        for (int i = t; i < IN_T; i += 512) {
            int c = i / 1156;
            int r = i - c * 1156;
            int y = r / 34 - 1;
            int x = r - (y + 1) * 34 - 1;
            float v = 0.0f;
            if ((unsigned)y < 32u && (unsigned)x < 32u)
                v = in[b * 16384 + y * 512 + x * 16 + c];
            sIn[i] = v;
        }
        __syncthreads();

        // Packed shifted accumulators: 2 positions x 8 filter-pairs.
        u64 sA[8], sB[8];
        #pragma unroll
        for (int k = 0; k < 8; k++) { sA[k] = 0ull; sB[k] = 0ull; }

        for (int kk = 0; kk < 9; kk++) {
            const int kh = kk / 3, kw = kk - kh * 3;
            const u64* g64base = reinterpret_cast<const u64*>(sG + (kk << 8));
            const int o = (y0 + kh) * 34 + (x0 + kw);
            #pragma unroll
            for (int c = 0; c < 16; c++) {
                const float* pc = sIn + c * 1156 + o;
                const u64 a0 = pk(pc[0]);
                const u64 a1 = pk(pc[16 * 34]);      // position 2: 16 rows down
                const u64* gc = g64base + (c << 3);
                #pragma unroll
                for (int k = 0; k < 8; k++) {
                    const u64 gk = gc[k];
                    FMA2(sA[k], a0, gk, sA[k]);
                    FMA2(sB[k], a1, gk, sB[k]);
                }
            }
        }

        // Epilogue: acc[c] = sum over this thread's 2 positions of
        //   m*iv - w*relu(iv - shifted)   (L = 1)
        float acc[16];
        {
            const int yx = t;
            const float wv = sW[yx], mv = sM[yx];
            const float* iv = sIn + (y0 + 1) * 34 + (x0 + 1);
            #pragma unroll
            for (int k = 0; k < 8; k++) {
                const float v0 = iv[(2 * k) * 1156];
                const float v1 = iv[(2 * k + 1) * 1156];
                acc[2 * k]     = mv * v0 - wv * fmaxf(v0 - lo32(sA[k]), 0.0f);
                acc[2 * k + 1] = mv * v1 - wv * fmaxf(v1 - hi32(sA[k]), 0.0f);
            }
        }
        {
            const int yx = t + 512;
            const float wv = sW[yx], mv = sM[yx];
            const float* iv = sIn + (y0 + 17) * 34 + (x0 + 1);
            #pragma unroll
            for (int k = 0; k < 8; k++) {
                const float v0 = iv[(2 * k) * 1156];
                const float v1 = iv[(2 * k + 1) * 1156];
                acc[2 * k]     += mv * v0 - wv * fmaxf(v0 - lo32(sB[k]), 0.0f);
                acc[2 * k + 1] += mv * v1 - wv * fmaxf(v1 - hi32(sB[k]), 0.0f);
            }
        }

        // Block reduction of acc[16] over 512 threads (16 warps).
        #pragma unroll
        for (int c = 0; c < 16; c++) {
            #pragma unroll
            for (int off = 16; off; off >>= 1)
                acc[c] += __shfl_down_sync(FULLMASK, acc[c], off);
        }
        if (lane == 0) {
            #pragma unroll
            for (int c = 0; c < 16; c++) sRed[warp * 16 + c] = acc[c];
        }
        __syncthreads();
        if (t < 16) {
            float sv = 0.0f;
            #pragma unroll
            for (int w16 = 0; w16 < 16; w16++) sv += sRed[w16 * 16 + t];
            out[b * 16384 + ij * 16 + t] = sv;
        }
    }
}

extern "C" void kernel_launch(void* const* d_in, const int* in_sizes, int n_in,
                              void* d_out, int out_size) {
    const float* in = (const float*)d_in[0];   // inputs (4,32,32,16)
    const float* Mm = (const float*)d_in[1];   // M (32,32,1,32,32,1)
    const float* Ww = (const float*)d_in[2];   // W (32,32,1,32,32,1)
    const float* Gg = (const float*)d_in[3];   // G (32,32,3,3,16,16)
    float* out = (float*)d_out;

    cudaFuncSetAttribute(inrf_kernel,
                         cudaFuncAttributeMaxDynamicSharedMemorySize, SMEM_BYTES);
    inrf_kernel<<<1024, 512, SMEM_BYTES>>>(in, Mm, Ww, Gg, out);
}

// round 8
// speedup vs baseline: 1.1680x; 1.1680x over previous
#include <cuda_runtime.h>

// INRF: out[b,i,j,c] = sum_yx M[ij,yx]*in[b,yx,c]
//                    - L * sum_yx W[ij,yx]*relu(in[b,yx,c] - shifted[b,ij,yx,c])
// shifted[b,ij,y,x,f] = sum_{kh,kw,c} in[b,y+kh-1,x+kw-1,c] * G[ij,kh,kw,c,f]
// B=4, H=W=32, C=F=16, KH=KW=3, L=1, SAME padding.
//
// One CTA per (i,j), 256 threads, 4 spatial positions per thread (R5's
// LDS-lean structure) with packed fma.rn.f32x2 math (R7's FLOP halving).
// Per (kk,c): 4x LDS.128 for G (reused across 4 positions) + 4x LDS.32 for
// input + 32 FFMA2. Register pairs uncapped (no min-blocks launch bound).

typedef unsigned long long u64;
#define FULLMASK 0xFFFFFFFFu

#define FMA2(d, a, b, c) \
    asm("fma.rn.f32x2 %0, %1, %2, %3;" : "=l"(d) : "l"(a), "l"(b), "l"(c))

__device__ __forceinline__ u64 pk(float x) {
    u64 v = (u64)__float_as_uint(x);
    return v | (v << 32);
}
__device__ __forceinline__ float lo32(u64 v) {
    return __uint_as_float((unsigned)v);
}
__device__ __forceinline__ float hi32(u64 v) {
    return __uint_as_float((unsigned)(v >> 32));
}

// SMEM layout (floats):
//  [0,2304)        G[ij]  : [kh][kw][c][f]
//  [2304,3328)     M row  : 1024
//  [3328,4352)     W row  : 1024
//  [4352,22848)    input tile, channel-major padded: [16][34][34]
//  [22848,23360)   reduction buffer (8 warps x 16)
#define OFF_M   2304
#define OFF_W   3328
#define OFF_IN  4352
#define OFF_RED 22848
#define SMEM_FLOATS 23360
#define SMEM_BYTES  (SMEM_FLOATS * 4)
#define IN_T (16 * 34 * 34)   // 18496

__global__ __launch_bounds__(256)
void inrf_kernel(const float* __restrict__ in,   // [4][32][32][16]
                 const float* __restrict__ Mm,   // [1024][1024]
                 const float* __restrict__ Ww,   // [1024][1024]
                 const float* __restrict__ Gg,   // [1024][3][3][16][16]
                 float* __restrict__ out)        // [4][32][32][16]
{
    extern __shared__ float sm[];
    float* sG   = sm;
    float* sM   = sm + OFF_M;
    float* sW   = sm + OFF_W;
    float* sIn  = sm + OFF_IN;
    float* sRed = sm + OFF_RED;

    const int ij = blockIdx.x;       // 0..1023
    const int t  = threadIdx.x;      // 0..255
    const int warp = t >> 5, lane = t & 31;

    // Load per-(i,j) weights
    for (int i = t; i < 2304; i += 256) sG[i] = Gg[ij * 2304 + i];
    for (int i = t; i < 1024; i += 256) {
        sM[i] = Mm[ij * 1024 + i];
        sW[i] = Ww[ij * 1024 + i];
    }

    // This thread's 4 positions: rows y0, y0+8, y0+16, y0+24; column x0.
    const int y0 = t >> 5;
    const int x0 = t & 31;

    for (int b = 0; b < 4; b++) {
        __syncthreads();  // protect sIn (and sRed/sG on first iter)
        // Load image b, channel-major, zero-padded: sIn[c*1156 + (y+1)*34 + (x+1)]
        for (int i = t; i < IN_T; i += 256) {
            int c = i / 1156;
            int r = i - c * 1156;
            int y = r / 34 - 1;
            int x = r - (y + 1) * 34 - 1;
            float v = 0.0f;
            if ((unsigned)y < 32u && (unsigned)x < 32u)
                v = in[b * 16384 + y * 512 + x * 16 + c];
            sIn[i] = v;
        }
        __syncthreads();

        // Packed shifted accumulators: 4 positions x 8 filter-pairs.
        u64 s[4][8];
        #pragma unroll
        for (int p = 0; p < 4; p++)
            #pragma unroll
            for (int k = 0; k < 8; k++) s[p][k] = 0ull;

        for (int kk = 0; kk < 9; kk++) {
            const int kh = kk / 3, kw = kk - kh * 3;
            const int o = (y0 + kh) * 34 + (x0 + kw);
            const ulonglong2* gq =
                reinterpret_cast<const ulonglong2*>(sG + (kk << 8));
            #pragma unroll
            for (int c = 0; c < 16; c++) {
                // 16 g floats = 8 u64 pairs = 4 x 128-bit loads, reused by 4 positions
                const ulonglong2 q0 = gq[(c << 2) + 0];
                const ulonglong2 q1 = gq[(c << 2) + 1];
                const ulonglong2 q2 = gq[(c << 2) + 2];
                const ulonglong2 q3 = gq[(c << 2) + 3];
                const float* pc = sIn + c * 1156 + o;
                #pragma unroll
                for (int p = 0; p < 4; p++) {
                    const u64 a = pk(pc[p * 272]);   // rows 8 apart (8*34)
                    FMA2(s[p][0], a, q0.x, s[p][0]);
                    FMA2(s[p][1], a, q0.y, s[p][1]);
                    FMA2(s[p][2], a, q1.x, s[p][2]);
                    FMA2(s[p][3], a, q1.y, s[p][3]);
                    FMA2(s[p][4], a, q2.x, s[p][4]);
                    FMA2(s[p][5], a, q2.y, s[p][5]);
                    FMA2(s[p][6], a, q3.x, s[p][6]);
                    FMA2(s[p][7], a, q3.y, s[p][7]);
                }
            }
        }

        // Epilogue: acc[c] = sum_p m_p*iv - w_p*relu(iv - shifted)   (L = 1)
        float acc[16];
        #pragma unroll
        for (int c = 0; c < 16; c++) acc[c] = 0.0f;
        #pragma unroll
        for (int p = 0; p < 4; p++) {
            const int yx = t + p * 256;
            const float wv = sW[yx], mv = sM[yx];
            const float* iv = sIn + (y0 + p * 8 + 1) * 34 + (x0 + 1);
            #pragma unroll
            for (int k = 0; k < 8; k++) {
                const float v0 = iv[(2 * k) * 1156];
                const float v1 = iv[(2 * k + 1) * 1156];
                acc[2 * k]     += mv * v0 - wv * fmaxf(v0 - lo32(s[p][k]), 0.0f);
                acc[2 * k + 1] += mv * v1 - wv * fmaxf(v1 - hi32(s[p][k]), 0.0f);
            }
        }

        // Block reduction of acc[16] over 256 threads (8 warps).
        #pragma unroll
        for (int c = 0; c < 16; c++) {
            #pragma unroll
            for (int off = 16; off; off >>= 1)
                acc[c] += __shfl_down_sync(FULLMASK, acc[c], off);
        }
        if (lane == 0) {
            #pragma unroll
            for (int c = 0; c < 16; c++) sRed[warp * 16 + c] = acc[c];
        }
        __syncthreads();
        if (t < 16) {
            float sv = 0.0f;
            #pragma unroll
            for (int w8 = 0; w8 < 8; w8++) sv += sRed[w8 * 16 + t];
            out[b * 16384 + ij * 16 + t] = sv;
        }
    }
}

extern "C" void kernel_launch(void* const* d_in, const int* in_sizes, int n_in,
                              void* d_out, int out_size) {
    const float* in = (const float*)d_in[0];   // inputs (4,32,32,16)
    const float* Mm = (const float*)d_in[1];   // M (32,32,1,32,32,1)
    const float* Ww = (const float*)d_in[2];   // W (32,32,1,32,32,1)
    const float* Gg = (const float*)d_in[3];   // G (32,32,3,3,16,16)
    float* out = (float*)d_out;

    cudaFuncSetAttribute(inrf_kernel,
                         cudaFuncAttributeMaxDynamicSharedMemorySize, SMEM_BYTES);
    inrf_kernel<<<1024, 256, SMEM_BYTES>>>(in, Mm, Ww, Gg, out);
}